// round 11
// baseline (speedup 1.0000x reference)
#include <cuda_runtime.h>

#define NMAX  1536
#define TPB   256
#define EPT   6          // strided elements per thread (NMAX / TPB)
#define NWARP 8
#define NITER 20

__device__ int g_maxdeg;

// ---------------------------------------------------------------------------
// Kernel 1 (pre): per-group offset (redundant prefix sum) + degree count
// -> global max degree via atomicMax.
// ---------------------------------------------------------------------------
__global__ void __launch_bounds__(512)
pre_kernel(const int* __restrict__ sizes,
           const int* __restrict__ edges,
           int N, int B) {
    __shared__ int cnt[NMAX];
    __shared__ int red[16];
    __shared__ int s_off;

    int g = blockIdx.x;
    int t = threadIdx.x;
    int lane = t & 31, wid = t >> 5;

    int part = 0;
    for (int i = t; i < g; i += 512) part += sizes[i];
#pragma unroll
    for (int d = 16; d; d >>= 1) part += __shfl_xor_sync(0xffffffffu, part, d);
    if (lane == 0) red[wid] = part;
    __syncthreads();
    if (t == 0) {
        int s = 0;
#pragma unroll
        for (int w = 0; w < 16; ++w) s += red[w];
        s_off = s;
    }
    int n = sizes[g];
    __syncthreads();
    int off = s_off;

    for (int i = t; i < n; i += 512)
        cnt[i] = (i == 0 || i == n - 1) ? 1 : 2;
    __syncthreads();

    const int2* e2 = (const int2*)edges;
    int reBase = (N - B) + off;
    for (int i = t; i < n; i += 512) {
        int2 e = e2[reBase + i];
        atomicAdd(&cnt[e.x - off], 1);
        atomicAdd(&cnt[e.y - off], 1);
    }
    __syncthreads();

    int m = 0;
    for (int i = t; i < n; i += 512) m = max(m, cnt[i]);
#pragma unroll
    for (int d = 16; d; d >>= 1) m = max(m, __shfl_xor_sync(0xffffffffu, m, d));
    if (lane == 0) red[wid] = m;
    __syncthreads();
    if (t == 0) {
        int mm = red[0];
#pragma unroll
        for (int w = 1; w < 16; ++w) mm = max(mm, red[w]);
        atomicMax(&g_maxdeg, mm);
    }
}

// ---------------------------------------------------------------------------
// Kernel 2 (main): fused per-group solve.
// Random edges counting-sorted by a-endpoint (conflict reduction);
// unique-slot stores + float4 gather; overflow (deg>4) via rare atomics;
// stable-edge store skip; Michelot sparsemax.
// sedge[] aliases ev[] (setup-only lifetime).
// ---------------------------------------------------------------------------
__global__ void __launch_bounds__(TPB, 3)
main_kernel(const float* __restrict__ x,
            const int*   __restrict__ sizes,
            const int*   __restrict__ edges,
            float*       __restrict__ out,
            int N, int B) {
    __shared__ float ys[NMAX];
    __shared__ float uc[NMAX];          // aliased as int arow[] during setup
    __shared__ float ev[4 * NMAX];      // 4 contribution slots per node; first NMAX words alias sedge during setup
    __shared__ float ovf[NMAX];         // overflow accum; aliased as int cnt[] during setup
    __shared__ float red_s[NWARP];
    __shared__ int   red_c[NWARP];
    __shared__ int   red_i[NWARP];
    __shared__ float s_tau;
    __shared__ int   s_cnt;
    __shared__ int   s_off;

    int g = blockIdx.x;
    int t = threadIdx.x;
    int lane = t & 31, wid = t >> 5;

    // offset[g] = sum of sizes[0..g)  (redundant recompute; L2-resident)
    {
        int part = 0;
        for (int i = t; i < g; i += TPB) part += sizes[i];
#pragma unroll
        for (int d = 16; d; d >>= 1) part += __shfl_xor_sync(0xffffffffu, part, d);
        if (lane == 0) red_i[wid] = part;
        __syncthreads();
        if (t == 0) {
            int s = 0;
#pragma unroll
            for (int w = 0; w < NWARP; ++w) s += red_i[w];
            s_off = s;
        }
    }
    int n = sizes[g];
    __syncthreads();
    int off = s_off;
    int reBase = (N - B) + off;

    int*      cnt   = (int*)ovf;
    int*      arow  = (int*)uc;
    unsigned* sedge = (unsigned*)ev;    // setup-only alias

    // per-element state
    float xr[EPT], yv[EPT], ucv[EPT];
    bool  hasovf[EPT];
    // per-(sorted)edge state — ea/eb reused: raw during setup, sorted after
    int   ea[EPT], eb[EPT];
    float ur[EPT];
    unsigned slp[EPT];

    // ---- setup: load x/edges; count a-degree ----
#pragma unroll
    for (int j = 0; j < EPT; ++j) {
        int i = t + j * TPB;
        cnt[i] = 0;
    }
    __syncthreads();

    const int2* e2 = (const int2*)edges;
#pragma unroll
    for (int j = 0; j < EPT; ++j) {
        int i = t + j * TPB;
        bool a = (j < 2) || (i < n);
        if (a) {
            xr[j] = x[off + i];
            int2 e = e2[reBase + i];
            ea[j] = e.x - off;
            eb[j] = e.y - off;
            ys[i] = xr[j];
            atomicAdd(&cnt[ea[j]], 1);
        } else {
            xr[j] = 0.0f; ea[j] = 0; eb[j] = 0;
            ys[i] = 0.0f;
        }
        yv[j]  = xr[j];
        ur[j]  = 0.0f;
        ucv[j] = 0.0f;
    }
    __syncthreads();

    // exclusive scan of a-degrees -> arow (contiguous 6 per thread)
    {
        int ib = 6 * t;
        int c0 = cnt[ib],     c1 = cnt[ib + 1], c2 = cnt[ib + 2];
        int c3 = cnt[ib + 3], c4 = cnt[ib + 4], c5 = cnt[ib + 5];
        int r0 = c0, r1 = r0 + c1, r2 = r1 + c2;
        int r3 = r2 + c3, r4 = r3 + c4, r5 = r4 + c5;
        int v = r5;
#pragma unroll
        for (int d = 1; d < 32; d <<= 1) {
            int o = __shfl_up_sync(0xffffffffu, v, d);
            if (lane >= d) v += o;
        }
        if (lane == 31) red_i[wid] = v;
        __syncthreads();
        if (wid == 0 && lane < NWARP) {
            int w = red_i[lane];
#pragma unroll
            for (int d = 1; d < NWARP; d <<= 1) {
                int o = __shfl_up_sync(0xffu, w, d);
                if (lane >= d) w += o;
            }
            red_i[lane] = w;
        }
        __syncthreads();
        int base = ((wid > 0) ? red_i[wid - 1] : 0) + (v - r5);
        arow[ib]     = base;
        arow[ib + 1] = base + r0;
        arow[ib + 2] = base + r1;
        arow[ib + 3] = base + r2;
        arow[ib + 4] = base + r3;
        arow[ib + 5] = base + r4;
    }
    __syncthreads();

    // reset cnt, then scatter edges into sedge sorted by ea
#pragma unroll
    for (int j = 0; j < EPT; ++j) cnt[t + j * TPB] = 0;
    __syncthreads();
#pragma unroll
    for (int j = 0; j < EPT; ++j) {
        int i = t + j * TPB;
        bool a = (j < 2) || (i < n);
        if (a) {
            int pos = arow[ea[j]] + atomicAdd(&cnt[ea[j]], 1);
            sedge[pos] = (unsigned)ea[j] | ((unsigned)eb[j] << 16);
        }
    }
    __syncthreads();

    // reset cnt; read sorted edges into registers; claim combined ev slots
#pragma unroll
    for (int j = 0; j < EPT; ++j) cnt[t + j * TPB] = 0;
    __syncthreads();
#pragma unroll
    for (int j = 0; j < EPT; ++j) {
        int p = t + j * TPB;
        bool a = (j < 2) || (p < n);
        if (a) {
            unsigned pk = sedge[p];
            ea[j] = (int)(pk & 0xFFFFu);
            eb[j] = (int)(pk >> 16);
        } else { ea[j] = 0; eb[j] = 0; }
    }
    __syncthreads();   // all sedge reads complete before ev is reused
#pragma unroll
    for (int j = 0; j < EPT; ++j) {
        int p = t + j * TPB;
        bool a = (j < 2) || (p < n);
        if (a) {
            int pa = atomicAdd(&cnt[ea[j]], 1);
            int pb = atomicAdd(&cnt[eb[j]], 1);
            unsigned sa = (pa < 4) ? (unsigned)(4 * ea[j] + pa) : 0xFFFFu;
            unsigned sb = (pb < 4) ? (unsigned)(4 * eb[j] + pb) : 0xFFFFu;
            slp[j] = sa | (sb << 16);
        } else {
            slp[j] = 0xFFFFu | (0xFFFFu << 16);
        }
    }
    __syncthreads();
#pragma unroll
    for (int j = 0; j < EPT; ++j) {
        int i = t + j * TPB;
        hasovf[j] = (cnt[i] > 4);
    }
    __syncthreads();
    // zero ev (overwrites sedge), ovf (aliases cnt), uc (aliases arow)
#pragma unroll
    for (int k = 0; k < 4 * EPT; ++k)
        ev[t + k * TPB] = 0.0f;
#pragma unroll
    for (int j = 0; j < EPT; ++j) {
        int i = t + j * TPB;
        ovf[i] = 0.0f;
        uc[i]  = 0.0f;
    }
    float step = 0.5f / (float)g_maxdeg;
    __syncthreads();

    // ---- 20 iterations, 2 barriers each ----
    for (int it = 0; it < NITER; ++it) {
        // Phase P1: chain duals (element ownership)
#pragma unroll
        for (int j = 0; j < EPT; ++j) {
            int i = t + j * TPB;
            bool a = (j < 2) || (i < n);
            if (a && i < n - 1) {
                float nu = ucv[j] + step * (yv[j] - ys[i + 1]);
                nu = fminf(1.0f, fmaxf(-1.0f, nu));
                ucv[j] = nu;
                uc[i] = nu;
            }
        }
        // Phase P2: random duals (sorted-edge ownership) + slot publish
#pragma unroll
        for (int j = 0; j < EPT; ++j) {
            int p = t + j * TPB;
            bool a = (j < 2) || (p < n);
            if (a) {
                float ya = ys[ea[j]], yb = ys[eb[j]];
                float nu = ur[j] + step * (ya - yb);
                nu = fminf(1.0f, fmaxf(-1.0f, nu));
                if (nu != ur[j]) {
                    unsigned sa = slp[j] & 0xFFFFu;
                    unsigned sb = slp[j] >> 16;
                    if (sa != 0xFFFFu) ev[sa] = -nu;
                    else               atomicAdd(&ovf[ea[j]], -(nu - ur[j]));
                    if (sb != 0xFFFFu) ev[sb] =  nu;
                    else               atomicAdd(&ovf[eb[j]],  (nu - ur[j]));
                    ur[j] = nu;
                }
            }
        }
        __syncthreads();
        // Phase R: rebuild y = x + uc[i-1] - uc[i] + sum(slots) [+ ovf]
#pragma unroll
        for (int j = 0; j < EPT; ++j) {
            int i = t + j * TPB;
            bool a = (j < 2) || (i < n);
            if (a) {
                float4 e4 = *(const float4*)&ev[4 * i];
                float v = xr[j] + ((e4.x + e4.y) + (e4.z + e4.w));
                if (hasovf[j]) v += ovf[i];
                if (i > 0)     v += uc[i - 1];
                if (i < n - 1) v -= ucv[j];
                yv[j] = v;
                ys[i] = v;
            }
        }
        __syncthreads();
    }

    // ---- sparsemax via Michelot (exact, no sort) ----
    {
        float s = 0.0f;
#pragma unroll
        for (int j = 0; j < EPT; ++j) {
            int i = t + j * TPB;
            if ((j < 2) || (i < n)) s += yv[j];
        }
#pragma unroll
        for (int d = 16; d; d >>= 1) s += __shfl_xor_sync(0xffffffffu, s, d);
        if (lane == 0) red_s[wid] = s;
        __syncthreads();
        if (t == 0) {
            float ss = 0.0f;
#pragma unroll
            for (int w = 0; w < NWARP; ++w) ss += red_s[w];
            s_tau = (ss - 1.0f) / (float)n;
            s_cnt = n;
        }
        __syncthreads();
    }

    float tau = s_tau;
    int prev_cnt = s_cnt;

    for (int itm = 0; itm < 64; ++itm) {
        float s = 0.0f;
        int   c = 0;
#pragma unroll
        for (int j = 0; j < EPT; ++j) {
            int i = t + j * TPB;
            bool a = (j < 2) || (i < n);
            if (a && yv[j] > tau) { s += yv[j]; ++c; }
        }
#pragma unroll
        for (int d = 16; d; d >>= 1) {
            s += __shfl_xor_sync(0xffffffffu, s, d);
            c += __shfl_xor_sync(0xffffffffu, c, d);
        }
        if (lane == 0) { red_s[wid] = s; red_c[wid] = c; }
        __syncthreads();
        if (t == 0) {
            float ss = 0.0f; int cc = 0;
#pragma unroll
            for (int w = 0; w < NWARP; ++w) { ss += red_s[w]; cc += red_c[w]; }
            s_tau = (ss - 1.0f) / (float)cc;
            s_cnt = cc;
        }
        __syncthreads();
        tau = s_tau;
        int cnt_now = s_cnt;
        if (cnt_now == prev_cnt) break;
        prev_cnt = cnt_now;
    }

    float scale = (float)n;
#pragma unroll
    for (int j = 0; j < EPT; ++j) {
        int i = t + j * TPB;
        if ((j < 2) || (i < n))
            out[off + i] = fmaxf(yv[j] - tau, 0.0f) * scale;
    }
}

// ---------------------------------------------------------------------------
extern "C" void kernel_launch(void* const* d_in, const int* in_sizes, int n_in,
                              void* d_out, int out_size) {
    const float* x     = (const float*)d_in[0];
    const int*   sizes = (const int*)  d_in[1];
    const int*   edges = (const int*)  d_in[2];
    float*       out   = (float*)d_out;
    int N = in_sizes[0];
    int B = in_sizes[1];

    pre_kernel<<<B, 512>>>(sizes, edges, N, B);
    main_kernel<<<B, TPB>>>(x, sizes, edges, out, N, B);
}

// round 12
// speedup vs baseline: 1.0553x; 1.0553x over previous
#include <cuda_runtime.h>

#define NMAX  1536
#define TPB   256
#define EPT   6          // strided elements per thread (NMAX / TPB)
#define NWARP 8
#define NITER 20

__device__ int g_maxdeg;

// ---------------------------------------------------------------------------
// Kernel 1 (pre): per-group offset (redundant prefix sum) + degree count
// -> global max degree via atomicMax.
// ---------------------------------------------------------------------------
__global__ void __launch_bounds__(512)
pre_kernel(const int* __restrict__ sizes,
           const int* __restrict__ edges,
           int N, int B) {
    __shared__ int cnt[NMAX];
    __shared__ int red[16];
    __shared__ int s_off;

    int g = blockIdx.x;
    int t = threadIdx.x;
    int lane = t & 31, wid = t >> 5;

    int part = 0;
    for (int i = t; i < g; i += 512) part += sizes[i];
#pragma unroll
    for (int d = 16; d; d >>= 1) part += __shfl_xor_sync(0xffffffffu, part, d);
    if (lane == 0) red[wid] = part;
    __syncthreads();
    if (t == 0) {
        int s = 0;
#pragma unroll
        for (int w = 0; w < 16; ++w) s += red[w];
        s_off = s;
    }
    int n = sizes[g];
    __syncthreads();
    int off = s_off;

    for (int i = t; i < n; i += 512)
        cnt[i] = (i == 0 || i == n - 1) ? 1 : 2;
    __syncthreads();

    const int2* e2 = (const int2*)edges;
    int reBase = (N - B) + off;
    for (int i = t; i < n; i += 512) {
        int2 e = e2[reBase + i];
        atomicAdd(&cnt[e.x - off], 1);
        atomicAdd(&cnt[e.y - off], 1);
    }
    __syncthreads();

    int m = 0;
    for (int i = t; i < n; i += 512) m = max(m, cnt[i]);
#pragma unroll
    for (int d = 16; d; d >>= 1) m = max(m, __shfl_xor_sync(0xffffffffu, m, d));
    if (lane == 0) red[wid] = m;
    __syncthreads();
    if (t == 0) {
        int mm = red[0];
#pragma unroll
        for (int w = 1; w < 16; ++w) mm = max(mm, red[w]);
        atomicMax(&g_maxdeg, mm);
    }
}

// ---------------------------------------------------------------------------
// Kernel 2 (main): fused per-group solve.
// Random edges counting-sorted by a-endpoint (conflict reduction);
// unique-slot UNCONDITIONAL stores + float4 gather; overflow (deg>4) via
// rare delta-atomics; Michelot sparsemax. sedge[] aliases ev[] (setup only).
// ---------------------------------------------------------------------------
__global__ void __launch_bounds__(TPB, 3)
main_kernel(const float* __restrict__ x,
            const int*   __restrict__ sizes,
            const int*   __restrict__ edges,
            float*       __restrict__ out,
            int N, int B) {
    __shared__ float ys[NMAX];
    __shared__ float uc[NMAX];          // aliased as int arow[] during setup
    __shared__ float ev[4 * NMAX];      // 4 slots per node; first NMAX words alias sedge during setup
    __shared__ float ovf[NMAX];         // overflow accum; aliased as int cnt[] during setup
    __shared__ float red_s[NWARP];
    __shared__ int   red_c[NWARP];
    __shared__ int   red_i[NWARP];
    __shared__ float s_tau;
    __shared__ int   s_cnt;
    __shared__ int   s_off;

    int g = blockIdx.x;
    int t = threadIdx.x;
    int lane = t & 31, wid = t >> 5;

    // offset[g] = sum of sizes[0..g)  (redundant recompute; L2-resident)
    {
        int part = 0;
        for (int i = t; i < g; i += TPB) part += sizes[i];
#pragma unroll
        for (int d = 16; d; d >>= 1) part += __shfl_xor_sync(0xffffffffu, part, d);
        if (lane == 0) red_i[wid] = part;
        __syncthreads();
        if (t == 0) {
            int s = 0;
#pragma unroll
            for (int w = 0; w < NWARP; ++w) s += red_i[w];
            s_off = s;
        }
    }
    int n = sizes[g];
    __syncthreads();
    int off = s_off;
    int reBase = (N - B) + off;

    int*      cnt   = (int*)ovf;
    int*      arow  = (int*)uc;
    unsigned* sedge = (unsigned*)ev;    // setup-only alias

    float xr[EPT], yv[EPT], ucv[EPT];
    bool  hasovf[EPT];
    int   ea[EPT], eb[EPT];
    float ur[EPT];
    unsigned slp[EPT];

    // ---- setup: load x/edges; count a-degree ----
#pragma unroll
    for (int j = 0; j < EPT; ++j) cnt[t + j * TPB] = 0;
    __syncthreads();

    const int2* e2 = (const int2*)edges;
#pragma unroll
    for (int j = 0; j < EPT; ++j) {
        int i = t + j * TPB;
        bool a = (j < 2) || (i < n);
        if (a) {
            xr[j] = x[off + i];
            int2 e = e2[reBase + i];
            ea[j] = e.x - off;
            eb[j] = e.y - off;
            ys[i] = xr[j];
            atomicAdd(&cnt[ea[j]], 1);
        } else {
            xr[j] = 0.0f; ea[j] = 0; eb[j] = 0;
            ys[i] = 0.0f;
        }
        yv[j]  = xr[j];
        ur[j]  = 0.0f;
        ucv[j] = 0.0f;
    }
    __syncthreads();

    // exclusive scan of a-degrees -> arow (contiguous 6 per thread)
    {
        int ib = 6 * t;
        int c0 = cnt[ib],     c1 = cnt[ib + 1], c2 = cnt[ib + 2];
        int c3 = cnt[ib + 3], c4 = cnt[ib + 4], c5 = cnt[ib + 5];
        int r0 = c0, r1 = r0 + c1, r2 = r1 + c2;
        int r3 = r2 + c3, r4 = r3 + c4, r5 = r4 + c5;
        int v = r5;
#pragma unroll
        for (int d = 1; d < 32; d <<= 1) {
            int o = __shfl_up_sync(0xffffffffu, v, d);
            if (lane >= d) v += o;
        }
        if (lane == 31) red_i[wid] = v;
        __syncthreads();
        if (wid == 0 && lane < NWARP) {
            int w = red_i[lane];
#pragma unroll
            for (int d = 1; d < NWARP; d <<= 1) {
                int o = __shfl_up_sync(0xffu, w, d);
                if (lane >= d) w += o;
            }
            red_i[lane] = w;
        }
        __syncthreads();
        int base = ((wid > 0) ? red_i[wid - 1] : 0) + (v - r5);
        arow[ib]     = base;
        arow[ib + 1] = base + r0;
        arow[ib + 2] = base + r1;
        arow[ib + 3] = base + r2;
        arow[ib + 4] = base + r3;
        arow[ib + 5] = base + r4;
    }
    __syncthreads();

    // reset cnt, then scatter edges into sedge sorted by ea
#pragma unroll
    for (int j = 0; j < EPT; ++j) cnt[t + j * TPB] = 0;
    __syncthreads();
#pragma unroll
    for (int j = 0; j < EPT; ++j) {
        int i = t + j * TPB;
        bool a = (j < 2) || (i < n);
        if (a) {
            int pos = arow[ea[j]] + atomicAdd(&cnt[ea[j]], 1);
            sedge[pos] = (unsigned)ea[j] | ((unsigned)eb[j] << 16);
        }
    }
    __syncthreads();

    // reset cnt; read sorted edges into registers
#pragma unroll
    for (int j = 0; j < EPT; ++j) cnt[t + j * TPB] = 0;
    __syncthreads();
#pragma unroll
    for (int j = 0; j < EPT; ++j) {
        int p = t + j * TPB;
        bool a = (j < 2) || (p < n);
        if (a) {
            unsigned pk = sedge[p];
            ea[j] = (int)(pk & 0xFFFFu);
            eb[j] = (int)(pk >> 16);
        } else { ea[j] = 0; eb[j] = 0; }
    }
    __syncthreads();   // all sedge reads complete before ev reuse
#pragma unroll
    for (int j = 0; j < EPT; ++j) {
        int p = t + j * TPB;
        bool a = (j < 2) || (p < n);
        if (a) {
            int pa = atomicAdd(&cnt[ea[j]], 1);
            int pb = atomicAdd(&cnt[eb[j]], 1);
            unsigned sa = (pa < 4) ? (unsigned)(4 * ea[j] + pa) : 0xFFFFu;
            unsigned sb = (pb < 4) ? (unsigned)(4 * eb[j] + pb) : 0xFFFFu;
            slp[j] = sa | (sb << 16);
        } else {
            slp[j] = 0xFFFFu | (0xFFFFu << 16);
        }
    }
    __syncthreads();
#pragma unroll
    for (int j = 0; j < EPT; ++j) {
        int i = t + j * TPB;
        hasovf[j] = (cnt[i] > 4);
    }
    __syncthreads();
    // zero ev (overwrites sedge), ovf (aliases cnt), uc (aliases arow)
#pragma unroll
    for (int k = 0; k < 4 * EPT; ++k)
        ev[t + k * TPB] = 0.0f;
#pragma unroll
    for (int j = 0; j < EPT; ++j) {
        int i = t + j * TPB;
        ovf[i] = 0.0f;
        uc[i]  = 0.0f;
    }
    float step = 0.5f / (float)g_maxdeg;
    __syncthreads();

    // ---- 20 iterations, 2 barriers each ----
    for (int it = 0; it < NITER; ++it) {
        // Phase P1: chain duals (element ownership)
#pragma unroll
        for (int j = 0; j < EPT; ++j) {
            int i = t + j * TPB;
            bool a = (j < 2) || (i < n);
            if (a && i < n - 1) {
                float nu = ucv[j] + step * (yv[j] - ys[i + 1]);
                nu = fminf(1.0f, fmaxf(-1.0f, nu));
                ucv[j] = nu;
                uc[i] = nu;
            }
        }
        // Phase P2: random duals (sorted-edge ownership), unconditional publish
#pragma unroll
        for (int j = 0; j < EPT; ++j) {
            int p = t + j * TPB;
            bool a = (j < 2) || (p < n);
            if (a) {
                float ya = ys[ea[j]], yb = ys[eb[j]];
                float nu = ur[j] + step * (ya - yb);
                nu = fminf(1.0f, fmaxf(-1.0f, nu));
                unsigned sa = slp[j] & 0xFFFFu;
                unsigned sb = slp[j] >> 16;
                if (sa != 0xFFFFu) ev[sa] = -nu;
                else               atomicAdd(&ovf[ea[j]], -(nu - ur[j]));
                if (sb != 0xFFFFu) ev[sb] =  nu;
                else               atomicAdd(&ovf[eb[j]],  (nu - ur[j]));
                ur[j] = nu;
            }
        }
        __syncthreads();
        // Phase R: rebuild y = x + uc[i-1] - uc[i] + sum(slots) [+ ovf]
#pragma unroll
        for (int j = 0; j < EPT; ++j) {
            int i = t + j * TPB;
            bool a = (j < 2) || (i < n);
            if (a) {
                float4 e4 = *(const float4*)&ev[4 * i];
                float v = xr[j] + ((e4.x + e4.y) + (e4.z + e4.w));
                if (hasovf[j]) v += ovf[i];
                if (i > 0)     v += uc[i - 1];
                if (i < n - 1) v -= ucv[j];
                yv[j] = v;
                ys[i] = v;
            }
        }
        __syncthreads();
    }

    // ---- sparsemax via Michelot (exact, no sort) ----
    {
        float s = 0.0f;
#pragma unroll
        for (int j = 0; j < EPT; ++j) {
            int i = t + j * TPB;
            if ((j < 2) || (i < n)) s += yv[j];
        }
#pragma unroll
        for (int d = 16; d; d >>= 1) s += __shfl_xor_sync(0xffffffffu, s, d);
        if (lane == 0) red_s[wid] = s;
        __syncthreads();
        if (t == 0) {
            float ss = 0.0f;
#pragma unroll
            for (int w = 0; w < NWARP; ++w) ss += red_s[w];
            s_tau = (ss - 1.0f) / (float)n;
            s_cnt = n;
        }
        __syncthreads();
    }

    float tau = s_tau;
    int prev_cnt = s_cnt;

    for (int itm = 0; itm < 64; ++itm) {
        float s = 0.0f;
        int   c = 0;
#pragma unroll
        for (int j = 0; j < EPT; ++j) {
            int i = t + j * TPB;
            bool a = (j < 2) || (i < n);
            if (a && yv[j] > tau) { s += yv[j]; ++c; }
        }
#pragma unroll
        for (int d = 16; d; d >>= 1) {
            s += __shfl_xor_sync(0xffffffffu, s, d);
            c += __shfl_xor_sync(0xffffffffu, c, d);
        }
        if (lane == 0) { red_s[wid] = s; red_c[wid] = c; }
        __syncthreads();
        if (t == 0) {
            float ss = 0.0f; int cc = 0;
#pragma unroll
            for (int w = 0; w < NWARP; ++w) { ss += red_s[w]; cc += red_c[w]; }
            s_tau = (ss - 1.0f) / (float)cc;
            s_cnt = cc;
        }
        __syncthreads();
        tau = s_tau;
        int cnt_now = s_cnt;
        if (cnt_now == prev_cnt) break;
        prev_cnt = cnt_now;
    }

    float scale = (float)n;
#pragma unroll
    for (int j = 0; j < EPT; ++j) {
        int i = t + j * TPB;
        if ((j < 2) || (i < n))
            out[off + i] = fmaxf(yv[j] - tau, 0.0f) * scale;
    }
}

// ---------------------------------------------------------------------------
extern "C" void kernel_launch(void* const* d_in, const int* in_sizes, int n_in,
                              void* d_out, int out_size) {
    const float* x     = (const float*)d_in[0];
    const int*   sizes = (const int*)  d_in[1];
    const int*   edges = (const int*)  d_in[2];
    float*       out   = (float*)d_out;
    int N = in_sizes[0];
    int B = in_sizes[1];

    pre_kernel<<<B, 512>>>(sizes, edges, N, B);
    main_kernel<<<B, TPB>>>(x, sizes, edges, out, N, B);
}